// round 13
// baseline (speedup 1.0000x reference)
#include <cuda_runtime.h>
#include <cuda_fp16.h>
#include <cstdint>

#define N_TOK   8192
#define S_CH    32
#define D_DIM   32
#define K_CODE  1024
#define IN_DIM  1024

#define M_TILE  128
#define THREADS 128
#define MCTA    (N_TOK / M_TILE)       // 64
#define NPART   (MCTA * S_CH)          // 2048
#define NTILES_TOT NPART
#define PERSIST_CTAS 740               // 5 per SM x 148

#define NCHUNK     8
#define CH_ROWS    128
#define ROW_BYTES  80                  // 32 halfs + 16B pad (ldmatrix bank-safe)
#define CH_BYTES   (CH_ROWS * ROW_BYTES)      // 10240

// ---------------- device scratch ----------------
__device__ float g_wsq[S_CH * K_CODE];
__device__ float g_partial[NPART];
__device__ unsigned int g_done = 0;
__device__ unsigned int g_tile = 0;
__device__ __align__(1024) unsigned char g_Wimg[S_CH * NCHUNK * CH_BYTES]; // 2.6MB

// ---------------- SMEM layout ----------------
#define SM_MBAR   0
#define SM_WSQ    64        // 4096
#define SM_ZH     4160      // 128 x 80B = 10240 (half(-2z) image)
#define SM_CANDV  14400     // 128 x 12 packed f32 = 6144
#define SM_LOSS   20544     // 512
#define SM_B0     21504     // 10240 (1024-aligned)
#define SM_B1     31744     // 10240
#define SMEM_TOTAL 41984

// ---------------- PTX helpers ----------------
__device__ __forceinline__ uint32_t smem_u32(const void* p) {
    uint32_t a;
    asm("{ .reg .u64 t; cvta.to.shared.u64 t, %1; cvt.u32.u64 %0, t; }" : "=r"(a) : "l"(p));
    return a;
}
#define MBAR_INIT(a, c) \
    asm volatile("mbarrier.init.shared.b64 [%0], %1;" :: "r"(a), "r"(c) : "memory")
#define MBAR_EXPECT(a, b) \
    asm volatile("mbarrier.arrive.expect_tx.shared.b64 _, [%0], %1;" :: "r"(a), "r"(b) : "memory")
#define MBAR_WAIT(a, ph) do { \
    uint32_t _m = (a); uint32_t _p = (ph); uint32_t _d; \
    asm volatile("{\n\t.reg .pred p;\n\t" \
        "mbarrier.try_wait.parity.acquire.cta.shared::cta.b64 p, [%1], %2;\n\t" \
        "selp.b32 %0, 1, 0, p;\n\t}" : "=r"(_d) : "r"(_m), "r"(_p) : "memory"); \
    if (!_d) { \
        asm volatile("{\n\t.reg .pred P1;\n\t" \
            "WL_%=:\n\t" \
            "mbarrier.try_wait.parity.acquire.cta.shared::cta.b64 P1, [%0], %1, 0x989680;\n\t" \
            "@P1 bra.uni WD_%=;\n\t" \
            "bra.uni WL_%=;\n\t" \
            "WD_%=:\n\t}" :: "r"(_m), "r"(_p) : "memory"); \
    } } while (0)

__device__ __forceinline__ void bulk_copy(uint32_t dst, const void* src, uint32_t bytes, uint32_t mbar) {
    uint64_t g = (uint64_t)__cvta_generic_to_global(src);
    asm volatile("cp.async.bulk.shared::cta.global.mbarrier::complete_tx::bytes [%0], [%1], %2, [%3];"
        :: "r"(dst), "l"(g), "r"(bytes), "r"(mbar) : "memory");
}
#define LDM_X4(r0, r1, r2, r3, a) \
    asm volatile("ldmatrix.sync.aligned.m8n8.x4.shared.b16 {%0,%1,%2,%3}, [%4];" \
        : "=r"(r0), "=r"(r1), "=r"(r2), "=r"(r3) : "r"(a))
#define MMA16816(c, a, b0, b1) \
    asm volatile("mma.sync.aligned.m16n8k16.row.col.f32.f16.f16.f32 " \
        "{%0,%1,%2,%3}, {%4,%5,%6,%7}, {%8,%9}, {%0,%1,%2,%3};" \
        : "+f"((c)[0]), "+f"((c)[1]), "+f"((c)[2]), "+f"((c)[3]) \
        : "r"((a)[0]), "r"((a)[1]), "r"((a)[2]), "r"((a)[3]), "r"(b0), "r"(b1))
#define MMA16816_INIT(c, a, b0, b1, c0v, c1v) \
    asm volatile("mma.sync.aligned.m16n8k16.row.col.f32.f16.f16.f32 " \
        "{%0,%1,%2,%3}, {%4,%5,%6,%7}, {%8,%9}, {%10,%11,%12,%13};" \
        : "=f"((c)[0]), "=f"((c)[1]), "=f"((c)[2]), "=f"((c)[3]) \
        : "r"((a)[0]), "r"((a)[1]), "r"((a)[2]), "r"((a)[3]), "r"(b0), "r"(b1), \
          "f"(c0v), "f"(c1v), "f"(c0v), "f"(c1v))

// pack k (10 bits) into low mantissa bits: ordering-preserving up to ~1.5e-2 abs
#define PPACK(v, k) __uint_as_float((__float_as_uint(v) & 0xFFFFFC00u) | (uint32_t)(k))

// per-row group epilogue: sorted lowest-2-of-4 network + merge into sorted top-3
#define LOW2MERGE(rw, v0, v1, v2, v3) do { \
    float _p0 = PPACK(v0, col0); \
    float _p1 = PPACK(v1, col0 + 1); \
    float _p2 = PPACK(v2, col2); \
    float _p3 = PPACK(v3, col2 + 1); \
    float _s1 = fminf(_p0, _p1), _t1 = fmaxf(_p0, _p1); \
    float _s2 = fminf(_p2, _p3), _t2 = fmaxf(_p2, _p3); \
    float _lo = fminf(_s1, _s2); \
    float _sec = fminf(fmaxf(_s1, _s2), fminf(_t1, _t2)); \
    float _m1 = fminf(c1[rw], _lo), _M1 = fmaxf(c1[rw], _lo); \
    float _m2 = fminf(c2[rw], _sec); \
    c1[rw] = _m1; \
    float _mx = fmaxf(_M1, _m2); \
    c2[rw] = fminf(_M1, _m2); \
    c3[rw] = fminf(c3[rw], _mx); } while (0)

// ---------------------------------------------------------------------------
// Kernel 1: prep — wsq + fp16 W image; also resets persistent counters
// ---------------------------------------------------------------------------
__global__ void prep_w(const float* __restrict__ W) {
    int i = blockIdx.x * blockDim.x + threadIdx.x;   // s*1024 + k
    if (i == 0) { g_tile = 0; g_done = 0; }          // reset for this replay
    if (i >= S_CH * K_CODE) return;
    int k = i & (K_CODE - 1);
    int s = i >> 10;
    int chunk = k >> 7, row = k & (CH_ROWS - 1);
    const float4* wr = reinterpret_cast<const float4*>(W + (size_t)i * D_DIM);

    float4 stage[5];
    __half2* oh = reinterpret_cast<__half2*>(stage);
    float sq = 0.f;
#pragma unroll
    for (int j = 0; j < 8; j++) {
        float4 v = __ldg(&wr[j]);
        sq = fmaf(v.x, v.x, sq); sq = fmaf(v.y, v.y, sq);
        sq = fmaf(v.z, v.z, sq); sq = fmaf(v.w, v.w, sq);
        oh[j * 2 + 0] = __floats2half2_rn(v.x, v.y);
        oh[j * 2 + 1] = __floats2half2_rn(v.z, v.w);
    }
#pragma unroll
    for (int j = 16; j < 20; j++) oh[j] = __floats2half2_rn(0.f, 0.f);

    float4* dst = reinterpret_cast<float4*>(
        g_Wimg + (size_t)(s * NCHUNK + chunk) * CH_BYTES + (size_t)row * ROW_BYTES);
#pragma unroll
    for (int j = 0; j < 5; j++) dst[j] = stage[j];
    g_wsq[i] = sq;
}

// ---------------------------------------------------------------------------
// Kernel 2: main — persistent CTAs, dynamic tile fetch, 2-stage SW pipeline
// ---------------------------------------------------------------------------
__global__ __launch_bounds__(THREADS, 5)
void vq_main(const float* __restrict__ z,
             const float* __restrict__ W,
             float* __restrict__ out,
             int out_size)
{
    extern __shared__ char smem[];
    const uint32_t sb = smem_u32(smem);
    const int tid  = threadIdx.x;
    const int wid  = tid >> 5;
    const int lane = tid & 31;

    float* s_wsq   = reinterpret_cast<float*>(smem + SM_WSQ);
    float* s_candv = reinterpret_cast<float*>(smem + SM_CANDV);
    float* s_loss  = reinterpret_cast<float*>(smem + SM_LOSS);

    __shared__ int  s_tile;
    __shared__ bool s_last;

    if (tid == 0) { MBAR_INIT(sb + SM_MBAR, 1); MBAR_INIT(sb + SM_MBAR + 8, 1); }
    __syncthreads();

    const int g   = lane >> 2;
    const int tig = lane & 3;
    const int bnrow = ((lane & 16) ? 8 : 0) + (lane & 7);
    const int bkb   = (lane >> 3) & 1;
    const uint32_t bbase = (uint32_t)bnrow * ROW_BYTES + bkb * 16;
    const int kb = (lane >> 4) & 1;

    for (;;) {
        // ---- fetch next tile (dynamic, deterministic output) ----
        if (tid == 0) s_tile = (int)atomicAdd(&g_tile, 1u);
        __syncthreads();
        const int tindex = s_tile;
        if (tindex >= NTILES_TOT) break;
        const int s  = tindex >> 6;
        const int n0 = (tindex & 63) * M_TILE;

        // kick off B copies for chunks 0, 1 (buffers free: prev tile fully read)
        if (tid == 0) {
            MBAR_EXPECT(sb + SM_MBAR, CH_BYTES);
            bulk_copy(sb + SM_B0, g_Wimg + (size_t)(s * NCHUNK + 0) * CH_BYTES, CH_BYTES, sb + SM_MBAR);
            MBAR_EXPECT(sb + SM_MBAR + 8, CH_BYTES);
            bulk_copy(sb + SM_B1, g_Wimg + (size_t)(s * NCHUNK + 1) * CH_BYTES, CH_BYTES, sb + SM_MBAR + 8);
        }

        // ---- stage A image half(-2z): one row per thread, + wsq ----
        {
            const int r = tid;
            const float4* zr = reinterpret_cast<const float4*>(
                z + (size_t)(n0 + r) * IN_DIM + s * D_DIM);
            float4 stage[5];
            __half2* zh = reinterpret_cast<__half2*>(stage);
#pragma unroll
            for (int j = 0; j < 4; j++) {
                float4 v0 = __ldg(&zr[j * 2 + 0]);
                float4 v1 = __ldg(&zr[j * 2 + 1]);
                zh[j * 4 + 0] = __floats2half2_rn(-2.f * v0.x, -2.f * v0.y);
                zh[j * 4 + 1] = __floats2half2_rn(-2.f * v0.z, -2.f * v0.w);
                zh[j * 4 + 2] = __floats2half2_rn(-2.f * v1.x, -2.f * v1.y);
                zh[j * 4 + 3] = __floats2half2_rn(-2.f * v1.z, -2.f * v1.w);
            }
#pragma unroll
            for (int j = 16; j < 20; j++) zh[j] = __floats2half2_rn(0.f, 0.f);
            float4* dst = reinterpret_cast<float4*>(smem + SM_ZH + r * ROW_BYTES);
#pragma unroll
            for (int j = 0; j < 5; j++) dst[j] = stage[j];
#pragma unroll
            for (int j = 0; j < K_CODE / THREADS; j++)
                s_wsq[tid + j * THREADS] = g_wsq[s * K_CODE + tid + j * THREADS];
        }
        __syncthreads();

        // ---- A fragments: 2 m16 blocks x 2 k-steps ----
        uint32_t Ah[2][2][4];
#pragma unroll
        for (int mb = 0; mb < 2; mb++) {
            const int rowoff = wid * 32 + mb * 16 + ((lane >> 3) & 1) * 8 + (lane & 7);
#pragma unroll
            for (int ks = 0; ks < 2; ks++) {
                uint32_t a = sb + SM_ZH + rowoff * ROW_BYTES + ks * 32 + kb * 16;
                LDM_X4(Ah[mb][ks][0], Ah[mb][ks][1], Ah[mb][ks][2], Ah[mb][ks][3], a);
            }
        }

        // per-thread: 4 row-streams, sorted packed top-3
        float c1[4], c2[4], c3[4];
#pragma unroll
        for (int c = 0; c < 4; c++) { c1[c] = 3.4e38f; c2[c] = 3.4e38f; c3[c] = 3.4e38f; }

        // double-buffered fragments / wsq / accumulators
        uint32_t bh0[2][4], bh1[2][4];
        float2   w01b[2], w23b[2];
        float a00[2][4], a01[2][4], a10[2][4], a11[2][4];

#pragma unroll 1
        for (int c = 0; c < NCHUNK; c++) {
            MBAR_WAIT(sb + SM_MBAR + (c & 1) * 8, (c >> 1) & 1);
            const uint32_t whb = sb + ((c & 1) ? SM_B1 : SM_B0);
            const int kch = c * CH_ROWS;

            LDM_X4(bh0[0][0], bh0[0][1], bh0[0][2], bh0[0][3], whb + bbase);
            LDM_X4(bh1[0][0], bh1[0][1], bh1[0][2], bh1[0][3], whb + bbase + 32);
            w01b[0] = *reinterpret_cast<const float2*>(&s_wsq[kch + tig * 2]);
            w23b[0] = *reinterpret_cast<const float2*>(&s_wsq[kch + 8 + tig * 2]);

#pragma unroll
            for (int g2 = 0; g2 < 8; g2++) {
                const int cur = g2 & 1, nxt = cur ^ 1;

                if (g2 < 7) {
                    const uint32_t boff = bbase + (uint32_t)(g2 + 1) * (16 * ROW_BYTES);
                    LDM_X4(bh0[nxt][0], bh0[nxt][1], bh0[nxt][2], bh0[nxt][3], whb + boff);
                    LDM_X4(bh1[nxt][0], bh1[nxt][1], bh1[nxt][2], bh1[nxt][3], whb + boff + 32);
                    const int kb2 = kch + (g2 + 1) * 16;
                    w01b[nxt] = *reinterpret_cast<const float2*>(&s_wsq[kb2 + tig * 2]);
                    w23b[nxt] = *reinterpret_cast<const float2*>(&s_wsq[kb2 + 8 + tig * 2]);
                }

                MMA16816_INIT(a00[cur], Ah[0][0], bh0[cur][0], bh0[cur][1], w01b[cur].x, w01b[cur].y);
                MMA16816     (a00[cur], Ah[0][1], bh1[cur][0], bh1[cur][1]);
                MMA16816_INIT(a01[cur], Ah[0][0], bh0[cur][2], bh0[cur][3], w23b[cur].x, w23b[cur].y);
                MMA16816     (a01[cur], Ah[0][1], bh1[cur][2], bh1[cur][3]);
                MMA16816_INIT(a10[cur], Ah[1][0], bh0[cur][0], bh0[cur][1], w01b[cur].x, w01b[cur].y);
                MMA16816     (a10[cur], Ah[1][1], bh1[cur][0], bh1[cur][1]);
                MMA16816_INIT(a11[cur], Ah[1][0], bh0[cur][2], bh0[cur][3], w23b[cur].x, w23b[cur].y);
                MMA16816     (a11[cur], Ah[1][1], bh1[cur][2], bh1[cur][3]);

                if (g2 > 0) {
                    const int kbase = kch + (g2 - 1) * 16;
                    const int col0 = kbase + tig * 2;
                    const int col2 = kbase + 8 + tig * 2;
                    LOW2MERGE(0, a00[nxt][0], a00[nxt][1], a01[nxt][0], a01[nxt][1]);
                    LOW2MERGE(1, a00[nxt][2], a00[nxt][3], a01[nxt][2], a01[nxt][3]);
                    LOW2MERGE(2, a10[nxt][0], a10[nxt][1], a11[nxt][0], a11[nxt][1]);
                    LOW2MERGE(3, a10[nxt][2], a10[nxt][3], a11[nxt][2], a11[nxt][3]);
                }
            }
            {
                const int kbase = kch + 7 * 16;
                const int col0 = kbase + tig * 2;
                const int col2 = kbase + 8 + tig * 2;
                LOW2MERGE(0, a00[1][0], a00[1][1], a01[1][0], a01[1][1]);
                LOW2MERGE(1, a00[1][2], a00[1][3], a01[1][2], a01[1][3]);
                LOW2MERGE(2, a10[1][0], a10[1][1], a11[1][0], a11[1][1]);
                LOW2MERGE(3, a10[1][2], a10[1][3], a11[1][2], a11[1][3]);
            }

            if (c + 1 < NCHUNK) {
                __syncthreads();
                if (tid == 0 && c + 2 < NCHUNK) {
                    MBAR_EXPECT(sb + SM_MBAR + (c & 1) * 8, CH_BYTES);
                    bulk_copy(sb + ((c & 1) ? SM_B1 : SM_B0),
                              g_Wimg + (size_t)(s * NCHUNK + c + 2) * CH_BYTES, CH_BYTES,
                              sb + SM_MBAR + (c & 1) * 8);
                }
            }
        }

        // ---- dump candidates: 12 packed per row (4 threads x top-3) ----
        {
            const int r0 = wid * 32 + g;
#pragma unroll
            for (int t = 0; t < 4; t++) {
                const int r = r0 + t * 8;
                s_candv[r * 12 + tig * 3 + 0] = c1[t];
                s_candv[r * 12 + tig * 3 + 1] = c2[t];
                s_candv[r * 12 + tig * 3 + 2] = c3[t];
            }
        }
        __syncwarp();   // candidates are warp-local: warp w owns rows 32w..32w+31

        // ---- band-filtered exact fp32 recheck: one thread per row ----
        {
            const int r = tid;
            float zr[D_DIM];
            {
                const float4* zg = reinterpret_cast<const float4*>(
                    z + (size_t)(n0 + r) * IN_DIM + s * D_DIM);
#pragma unroll
                for (int j = 0; j < 8; j++) {
                    float4 v = __ldg(&zg[j]);
                    zr[j * 4 + 0] = v.x; zr[j * 4 + 1] = v.y;
                    zr[j * 4 + 2] = v.z; zr[j * 4 + 3] = v.w;
                }
            }
            float zsq = 0.f;
#pragma unroll
            for (int d = 0; d < D_DIM; d++) zsq = fmaf(zr[d], zr[d], zsq);

            float m = 3.4e38f;
#pragma unroll
            for (int j = 0; j < 12; j++) m = fminf(m, s_candv[r * 12 + j]);
            const float thr = m + 0.06f;

            float bestd = 3.4e38f;
            int   besti = K_CODE;
#pragma unroll 1
            for (int j = 0; j < 12; j++) {
                float pv = s_candv[r * 12 + j];
                if (pv > thr) continue;
                int k = (int)(__float_as_uint(pv) & 0x3FFu);
                const float4* wr = reinterpret_cast<const float4*>(
                    W + ((size_t)s * K_CODE + k) * D_DIM);
                float dot = 0.f;
#pragma unroll
                for (int jj = 0; jj < 8; jj++) {
                    float4 vv = __ldg(&wr[jj]);
                    dot = fmaf(zr[jj * 4 + 0], vv.x, dot);
                    dot = fmaf(zr[jj * 4 + 1], vv.y, dot);
                    dot = fmaf(zr[jj * 4 + 2], vv.z, dot);
                    dot = fmaf(zr[jj * 4 + 3], vv.w, dot);
                }
                float d2 = (zsq + s_wsq[k]) - 2.0f * dot;
                if (d2 < bestd || (d2 == bestd && k < besti)) { bestd = d2; besti = k; }
            }

            // gather winner, write output row-chunk, loss contribution
            const float4* wr = reinterpret_cast<const float4*>(
                W + ((size_t)s * K_CODE + besti) * D_DIM);
            float4* orow = reinterpret_cast<float4*>(
                out + (size_t)(n0 + r) * IN_DIM + s * D_DIM);
            float ls = 0.f;
#pragma unroll
            for (int j = 0; j < 8; j++) {
                float4 vv = __ldg(&wr[j]);
                float a0 = vv.x - zr[j * 4 + 0];
                float a1 = vv.y - zr[j * 4 + 1];
                float a2 = vv.z - zr[j * 4 + 2];
                float a3 = vv.w - zr[j * 4 + 3];
                ls = fmaf(a0, a0, ls); ls = fmaf(a1, a1, ls);
                ls = fmaf(a2, a2, ls); ls = fmaf(a3, a3, ls);
                orow[j] = vv;
            }
            s_loss[r] = ls;
        }
        __syncthreads();

        if (tid == 0) {
            float acc = 0.f;
#pragma unroll
            for (int q = 0; q < M_TILE; q++) acc += s_loss[q];
            g_partial[tindex] = acc;
        }

        // ---- fused deterministic finalize: last tile reduces all partials ----
        __threadfence();
        if (tid == 0) {
            unsigned int t = atomicAdd(&g_done, 1u);
            s_last = (t == (unsigned int)(NPART - 1));
        }
        __syncthreads();
        if (s_last) {
            float a = 0.f;
            for (int i = tid; i < NPART; i += THREADS) a += g_partial[i];   // fixed order
            float* red = s_candv;       // safe: this CTA's tile is complete
            red[tid] = a;
            __syncthreads();
#pragma unroll
            for (int off = 64; off > 0; off >>= 1) {
                if (tid < off) red[tid] += red[tid + off];
                __syncthreads();
            }
            if (tid == 0) {
                float mm = red[0] / (float)((size_t)N_TOK * S_CH * D_DIM);
                float loss = (float)S_CH * (mm + 0.001f * mm);
                if (out_size > N_TOK * IN_DIM) out[out_size - 1] = loss;
            }
            __syncthreads();
        }
    }
}

// ---------------------------------------------------------------------------
extern "C" void kernel_launch(void* const* d_in, const int* in_sizes, int n_in,
                              void* d_out, int out_size) {
    const float* z = (const float*)d_in[0];   // (8192, 1024) f32
    const float* W = (const float*)d_in[1];   // (32, 1024, 32) f32
    float* out = (float*)d_out;

    cudaFuncSetAttribute(vq_main, cudaFuncAttributeMaxDynamicSharedMemorySize, SMEM_TOTAL);

    prep_w<<<(S_CH * K_CODE + 255) / 256, 256>>>(W);

    vq_main<<<PERSIST_CTAS, THREADS, SMEM_TOTAL>>>(z, W, out, out_size);
}

// round 14
// speedup vs baseline: 1.0884x; 1.0884x over previous
#include <cuda_runtime.h>
#include <cuda_fp16.h>
#include <cstdint>

#define N_TOK   8192
#define S_CH    32
#define D_DIM   32
#define K_CODE  1024
#define IN_DIM  1024

#define M_TILE  128
#define THREADS 128
#define MCTA    (N_TOK / M_TILE)       // 64
#define NPART   (MCTA * S_CH)          // 2048

#define NCHUNK     8
#define CH_ROWS    128
#define ROW_BYTES  80                  // 32 halfs + 16B pad (ldmatrix bank-safe)
#define CH_BYTES   (CH_ROWS * ROW_BYTES)      // 10240

// ---------------- device scratch ----------------
__device__ float g_wsq[S_CH * K_CODE];
__device__ float g_partial[NPART];
__device__ unsigned int g_done = 0;
__device__ __align__(1024) unsigned char g_Wimg[S_CH * NCHUNK * CH_BYTES]; // 2.6MB

// ---------------- SMEM layout ----------------
#define SM_MBAR   0         // ready[0], ready[1], free[0], free[1] (8B each)
#define SM_WSQ    64        // 4096
#define SM_ZH     4160      // 128 x 80B = 10240 (half(-2z) image)
#define SM_CANDV  14400     // 128 x 12 packed f32 = 6144
#define SM_LOSS   20544     // 512
#define SM_B0     21504     // 10240 (1024-aligned)
#define SM_B1     31744     // 10240
#define SMEM_TOTAL 41984

// ---------------- PTX helpers ----------------
__device__ __forceinline__ uint32_t smem_u32(const void* p) {
    uint32_t a;
    asm("{ .reg .u64 t; cvta.to.shared.u64 t, %1; cvt.u32.u64 %0, t; }" : "=r"(a) : "l"(p));
    return a;
}
#define MBAR_INIT(a, c) \
    asm volatile("mbarrier.init.shared.b64 [%0], %1;" :: "r"(a), "r"(c) : "memory")
#define MBAR_EXPECT(a, b) \
    asm volatile("mbarrier.arrive.expect_tx.shared.b64 _, [%0], %1;" :: "r"(a), "r"(b) : "memory")
#define MBAR_ARRIVE(a) \
    asm volatile("mbarrier.arrive.shared.b64 _, [%0];" :: "r"(a) : "memory")
#define MBAR_WAIT(a, ph) do { \
    uint32_t _m = (a); uint32_t _p = (ph); uint32_t _d; \
    asm volatile("{\n\t.reg .pred p;\n\t" \
        "mbarrier.try_wait.parity.acquire.cta.shared::cta.b64 p, [%1], %2;\n\t" \
        "selp.b32 %0, 1, 0, p;\n\t}" : "=r"(_d) : "r"(_m), "r"(_p) : "memory"); \
    if (!_d) { \
        asm volatile("{\n\t.reg .pred P1;\n\t" \
            "WL_%=:\n\t" \
            "mbarrier.try_wait.parity.acquire.cta.shared::cta.b64 P1, [%0], %1, 0x989680;\n\t" \
            "@P1 bra.uni WD_%=;\n\t" \
            "bra.uni WL_%=;\n\t" \
            "WD_%=:\n\t}" :: "r"(_m), "r"(_p) : "memory"); \
    } } while (0)

__device__ __forceinline__ void bulk_copy(uint32_t dst, const void* src, uint32_t bytes, uint32_t mbar) {
    uint64_t g = (uint64_t)__cvta_generic_to_global(src);
    asm volatile("cp.async.bulk.shared::cta.global.mbarrier::complete_tx::bytes [%0], [%1], %2, [%3];"
        :: "r"(dst), "l"(g), "r"(bytes), "r"(mbar) : "memory");
}
#define LDM_X4(r0, r1, r2, r3, a) \
    asm volatile("ldmatrix.sync.aligned.m8n8.x4.shared.b16 {%0,%1,%2,%3}, [%4];" \
        : "=r"(r0), "=r"(r1), "=r"(r2), "=r"(r3) : "r"(a))
#define MMA16816(c, a, b0, b1) \
    asm volatile("mma.sync.aligned.m16n8k16.row.col.f32.f16.f16.f32 " \
        "{%0,%1,%2,%3}, {%4,%5,%6,%7}, {%8,%9}, {%0,%1,%2,%3};" \
        : "+f"((c)[0]), "+f"((c)[1]), "+f"((c)[2]), "+f"((c)[3]) \
        : "r"((a)[0]), "r"((a)[1]), "r"((a)[2]), "r"((a)[3]), "r"(b0), "r"(b1))
#define MMA16816_INIT(c, a, b0, b1, c0v, c1v) \
    asm volatile("mma.sync.aligned.m16n8k16.row.col.f32.f16.f16.f32 " \
        "{%0,%1,%2,%3}, {%4,%5,%6,%7}, {%8,%9}, {%10,%11,%12,%13};" \
        : "=f"((c)[0]), "=f"((c)[1]), "=f"((c)[2]), "=f"((c)[3]) \
        : "r"((a)[0]), "r"((a)[1]), "r"((a)[2]), "r"((a)[3]), "r"(b0), "r"(b1), \
          "f"(c0v), "f"(c1v), "f"(c0v), "f"(c1v))

// pack k (10 bits) into low mantissa bits: ordering-preserving up to ~1.5e-2 abs
#define PPACK(v, k) __uint_as_float((__float_as_uint(v) & 0xFFFFFC00u) | (uint32_t)(k))

// per-row group epilogue: sorted lowest-2-of-4 network + merge into sorted top-3
#define LOW2MERGE(rw, v0, v1, v2, v3) do { \
    float _p0 = PPACK(v0, col0); \
    float _p1 = PPACK(v1, col0 + 1); \
    float _p2 = PPACK(v2, col2); \
    float _p3 = PPACK(v3, col2 + 1); \
    float _s1 = fminf(_p0, _p1), _t1 = fmaxf(_p0, _p1); \
    float _s2 = fminf(_p2, _p3), _t2 = fmaxf(_p2, _p3); \
    float _lo = fminf(_s1, _s2); \
    float _sec = fminf(fmaxf(_s1, _s2), fminf(_t1, _t2)); \
    float _m1 = fminf(c1[rw], _lo), _M1 = fmaxf(c1[rw], _lo); \
    float _m2 = fminf(c2[rw], _sec); \
    c1[rw] = _m1; \
    float _mx = fmaxf(_M1, _m2); \
    c2[rw] = fminf(_M1, _m2); \
    c3[rw] = fminf(c3[rw], _mx); } while (0)

// ---------------------------------------------------------------------------
// Kernel 1: prep — wsq + fp16 W image; row staged in regs, 5x ST.128
// ---------------------------------------------------------------------------
__global__ void prep_w(const float* __restrict__ W) {
    int i = blockIdx.x * blockDim.x + threadIdx.x;   // s*1024 + k
    if (i >= S_CH * K_CODE) return;
    int k = i & (K_CODE - 1);
    int s = i >> 10;
    int chunk = k >> 7, row = k & (CH_ROWS - 1);
    const float4* wr = reinterpret_cast<const float4*>(W + (size_t)i * D_DIM);

    float4 stage[5];
    __half2* oh = reinterpret_cast<__half2*>(stage);
    float sq = 0.f;
#pragma unroll
    for (int j = 0; j < 8; j++) {
        float4 v = __ldg(&wr[j]);
        sq = fmaf(v.x, v.x, sq); sq = fmaf(v.y, v.y, sq);
        sq = fmaf(v.z, v.z, sq); sq = fmaf(v.w, v.w, sq);
        oh[j * 2 + 0] = __floats2half2_rn(v.x, v.y);
        oh[j * 2 + 1] = __floats2half2_rn(v.z, v.w);
    }
#pragma unroll
    for (int j = 16; j < 20; j++) oh[j] = __floats2half2_rn(0.f, 0.f);

    float4* dst = reinterpret_cast<float4*>(
        g_Wimg + (size_t)(s * NCHUNK + chunk) * CH_BYTES + (size_t)row * ROW_BYTES);
#pragma unroll
    for (int j = 0; j < 5; j++) dst[j] = stage[j];
    g_wsq[i] = sq;
}

// ---------------------------------------------------------------------------
// Kernel 2: main — 4-warp CTA, warp-decoupled chunk pipeline (mbarrier
// produce/consume, no block barriers in the mainloop), packed top-3
// ---------------------------------------------------------------------------
__global__ __launch_bounds__(THREADS, 4)
void vq_main(const float* __restrict__ z,
             const float* __restrict__ W,
             float* __restrict__ out,
             int out_size)
{
    extern __shared__ char smem[];
    const uint32_t sb = smem_u32(smem);
    const int tid  = threadIdx.x;
    const int wid  = tid >> 5;
    const int lane = tid & 31;
    const int s    = blockIdx.y;
    const int n0   = blockIdx.x * M_TILE;

    float* s_wsq   = reinterpret_cast<float*>(smem + SM_WSQ);
    float* s_candv = reinterpret_cast<float*>(smem + SM_CANDV);
    float* s_loss  = reinterpret_cast<float*>(smem + SM_LOSS);

    const uint32_t mb_ready0 = sb + SM_MBAR;
    const uint32_t mb_ready1 = sb + SM_MBAR + 8;
    const uint32_t mb_free0  = sb + SM_MBAR + 16;
    const uint32_t mb_free1  = sb + SM_MBAR + 24;

    if (tid == 0) {
        MBAR_INIT(mb_ready0, 1); MBAR_INIT(mb_ready1, 1);
        MBAR_INIT(mb_free0, THREADS); MBAR_INIT(mb_free1, THREADS);
    }
    __syncthreads();

    if (tid == 0) {
        MBAR_EXPECT(mb_ready0, CH_BYTES);
        bulk_copy(sb + SM_B0, g_Wimg + (size_t)(s * NCHUNK + 0) * CH_BYTES, CH_BYTES, mb_ready0);
        MBAR_EXPECT(mb_ready1, CH_BYTES);
        bulk_copy(sb + SM_B1, g_Wimg + (size_t)(s * NCHUNK + 1) * CH_BYTES, CH_BYTES, mb_ready1);
    }

    // ---- stage A image half(-2z): one row per thread, + wsq ----
    {
        const int r = tid;                      // 0..127
        const float4* zr = reinterpret_cast<const float4*>(
            z + (size_t)(n0 + r) * IN_DIM + s * D_DIM);
        float4 stage[5];
        __half2* zh = reinterpret_cast<__half2*>(stage);
#pragma unroll
        for (int j = 0; j < 4; j++) {
            float4 v0 = __ldg(&zr[j * 2 + 0]);
            float4 v1 = __ldg(&zr[j * 2 + 1]);
            zh[j * 4 + 0] = __floats2half2_rn(-2.f * v0.x, -2.f * v0.y);
            zh[j * 4 + 1] = __floats2half2_rn(-2.f * v0.z, -2.f * v0.w);
            zh[j * 4 + 2] = __floats2half2_rn(-2.f * v1.x, -2.f * v1.y);
            zh[j * 4 + 3] = __floats2half2_rn(-2.f * v1.z, -2.f * v1.w);
        }
#pragma unroll
        for (int j = 16; j < 20; j++) zh[j] = __floats2half2_rn(0.f, 0.f);
        float4* dst = reinterpret_cast<float4*>(smem + SM_ZH + r * ROW_BYTES);
#pragma unroll
        for (int j = 0; j < 5; j++) dst[j] = stage[j];
#pragma unroll
        for (int j = 0; j < K_CODE / THREADS; j++)
            s_wsq[tid + j * THREADS] = g_wsq[s * K_CODE + tid + j * THREADS];
    }
    __syncthreads();   // A image + wsq visible to all warps

    // ---- A fragments: 2 m16 blocks x 2 k-steps ----
    uint32_t Ah[2][2][4];
    {
        const int kb = (lane >> 4) & 1;
#pragma unroll
        for (int mb = 0; mb < 2; mb++) {
            const int rowoff = wid * 32 + mb * 16 + ((lane >> 3) & 1) * 8 + (lane & 7);
#pragma unroll
            for (int ks = 0; ks < 2; ks++) {
                uint32_t a = sb + SM_ZH + rowoff * ROW_BYTES + ks * 32 + kb * 16;
                LDM_X4(Ah[mb][ks][0], Ah[mb][ks][1], Ah[mb][ks][2], Ah[mb][ks][3], a);
            }
        }
    }

    const int g   = lane >> 2;
    const int tig = lane & 3;

    // per-thread: 4 row-streams (rows wid*32 + g + {0,8,16,24}), sorted top-3
    float c1[4], c2[4], c3[4];
#pragma unroll
    for (int c = 0; c < 4; c++) { c1[c] = 3.4e38f; c2[c] = 3.4e38f; c3[c] = 3.4e38f; }

    const int bnrow = ((lane & 16) ? 8 : 0) + (lane & 7);
    const int bkb   = (lane >> 3) & 1;
    const uint32_t bbase = (uint32_t)bnrow * ROW_BYTES + bkb * 16;

    // double-buffered fragments / wsq / accumulators (2-stage SW pipeline)
    uint32_t bh0[2][4], bh1[2][4];
    float2   w01b[2], w23b[2];
    float a00[2][4], a01[2][4], a10[2][4], a11[2][4];

#pragma unroll 1
    for (int c = 0; c < NCHUNK; c++) {
        const uint32_t mb_ready = (c & 1) ? mb_ready1 : mb_ready0;
        const uint32_t mb_free  = (c & 1) ? mb_free1  : mb_free0;
        MBAR_WAIT(mb_ready, (c >> 1) & 1);   // per-thread: proceed as soon as data lands
        const uint32_t whb = sb + ((c & 1) ? SM_B1 : SM_B0);
        const int kch = c * CH_ROWS;

        // prologue: fragments + wsq for g2 = 0
        {
            LDM_X4(bh0[0][0], bh0[0][1], bh0[0][2], bh0[0][3], whb + bbase);
            LDM_X4(bh1[0][0], bh1[0][1], bh1[0][2], bh1[0][3], whb + bbase + 32);
            w01b[0] = *reinterpret_cast<const float2*>(&s_wsq[kch + tig * 2]);
            w23b[0] = *reinterpret_cast<const float2*>(&s_wsq[kch + 8 + tig * 2]);
        }

#pragma unroll
        for (int g2 = 0; g2 < 8; g2++) {
            const int cur = g2 & 1, nxt = cur ^ 1;

            if (g2 < 7) {
                const uint32_t boff = bbase + (uint32_t)(g2 + 1) * (16 * ROW_BYTES);
                LDM_X4(bh0[nxt][0], bh0[nxt][1], bh0[nxt][2], bh0[nxt][3], whb + boff);
                LDM_X4(bh1[nxt][0], bh1[nxt][1], bh1[nxt][2], bh1[nxt][3], whb + boff + 32);
                const int kb2 = kch + (g2 + 1) * 16;
                w01b[nxt] = *reinterpret_cast<const float2*>(&s_wsq[kb2 + tig * 2]);
                w23b[nxt] = *reinterpret_cast<const float2*>(&s_wsq[kb2 + 8 + tig * 2]);
            }

            MMA16816_INIT(a00[cur], Ah[0][0], bh0[cur][0], bh0[cur][1], w01b[cur].x, w01b[cur].y);
            MMA16816     (a00[cur], Ah[0][1], bh1[cur][0], bh1[cur][1]);
            MMA16816_INIT(a01[cur], Ah[0][0], bh0[cur][2], bh0[cur][3], w23b[cur].x, w23b[cur].y);
            MMA16816     (a01[cur], Ah[0][1], bh1[cur][2], bh1[cur][3]);
            MMA16816_INIT(a10[cur], Ah[1][0], bh0[cur][0], bh0[cur][1], w01b[cur].x, w01b[cur].y);
            MMA16816     (a10[cur], Ah[1][1], bh1[cur][0], bh1[cur][1]);
            MMA16816_INIT(a11[cur], Ah[1][0], bh0[cur][2], bh0[cur][3], w23b[cur].x, w23b[cur].y);
            MMA16816     (a11[cur], Ah[1][1], bh1[cur][2], bh1[cur][3]);

            if (g2 > 0) {
                const int kbase = kch + (g2 - 1) * 16;
                const int col0 = kbase + tig * 2;
                const int col2 = kbase + 8 + tig * 2;
                LOW2MERGE(0, a00[nxt][0], a00[nxt][1], a01[nxt][0], a01[nxt][1]);
                LOW2MERGE(1, a00[nxt][2], a00[nxt][3], a01[nxt][2], a01[nxt][3]);
                LOW2MERGE(2, a10[nxt][0], a10[nxt][1], a11[nxt][0], a11[nxt][1]);
                LOW2MERGE(3, a10[nxt][2], a10[nxt][3], a11[nxt][2], a11[nxt][3]);
            }
        }
        // drain: epilogue for g2 = 7 (buffer 1)
        {
            const int kbase = kch + 7 * 16;
            const int col0 = kbase + tig * 2;
            const int col2 = kbase + 8 + tig * 2;
            LOW2MERGE(0, a00[1][0], a00[1][1], a01[1][0], a01[1][1]);
            LOW2MERGE(1, a00[1][2], a00[1][3], a01[1][2], a01[1][3]);
            LOW2MERGE(2, a10[1][0], a10[1][1], a11[1][0], a11[1][1]);
            LOW2MERGE(3, a10[1][2], a10[1][3], a11[1][2], a11[1][3]);
        }

        // release this buffer (non-blocking); warps may skew into chunk c+1
        MBAR_ARRIVE(mb_free);
        if (tid == 0 && c + 2 < NCHUNK) {
            // producer: wait until ALL threads released buffer, then refill
            MBAR_WAIT(mb_free, (c >> 1) & 1);
            MBAR_EXPECT(mb_ready, CH_BYTES);
            bulk_copy(whb, g_Wimg + (size_t)(s * NCHUNK + c + 2) * CH_BYTES, CH_BYTES, mb_ready);
        }
    }

    // ---- dump candidates: 12 packed per row (4 threads x top-3) ----
    {
        const int r0 = wid * 32 + g;
#pragma unroll
        for (int t = 0; t < 4; t++) {
            const int r = r0 + t * 8;
            s_candv[r * 12 + tig * 3 + 0] = c1[t];
            s_candv[r * 12 + tig * 3 + 1] = c2[t];
            s_candv[r * 12 + tig * 3 + 2] = c3[t];
        }
    }
    __syncwarp();   // candidates are warp-local: warp w owns rows 32w..32w+31

    // ---- band-filtered exact fp32 recheck: one thread per row ----
    {
        const int r = tid;
        float zr[D_DIM];
        {
            const float4* zg = reinterpret_cast<const float4*>(
                z + (size_t)(n0 + r) * IN_DIM + s * D_DIM);
#pragma unroll
            for (int j = 0; j < 8; j++) {
                float4 v = __ldg(&zg[j]);
                zr[j * 4 + 0] = v.x; zr[j * 4 + 1] = v.y;
                zr[j * 4 + 2] = v.z; zr[j * 4 + 3] = v.w;
            }
        }
        float zsq = 0.f;
#pragma unroll
        for (int d = 0; d < D_DIM; d++) zsq = fmaf(zr[d], zr[d], zsq);

        float m = 3.4e38f;
#pragma unroll
        for (int j = 0; j < 12; j++) m = fminf(m, s_candv[r * 12 + j]);
        const float thr = m + 0.06f;

        float bestd = 3.4e38f;
        int   besti = K_CODE;
#pragma unroll 1
        for (int j = 0; j < 12; j++) {
            float pv = s_candv[r * 12 + j];
            if (pv > thr) continue;
            int k = (int)(__float_as_uint(pv) & 0x3FFu);
            const float4* wr = reinterpret_cast<const float4*>(
                W + ((size_t)s * K_CODE + k) * D_DIM);
            float dot = 0.f;
#pragma unroll
            for (int jj = 0; jj < 8; jj++) {
                float4 vv = __ldg(&wr[jj]);
                dot = fmaf(zr[jj * 4 + 0], vv.x, dot);
                dot = fmaf(zr[jj * 4 + 1], vv.y, dot);
                dot = fmaf(zr[jj * 4 + 2], vv.z, dot);
                dot = fmaf(zr[jj * 4 + 3], vv.w, dot);
            }
            float d2 = (zsq + s_wsq[k]) - 2.0f * dot;
            if (d2 < bestd || (d2 == bestd && k < besti)) { bestd = d2; besti = k; }
        }

        // gather winner, write output row-chunk, loss contribution
        const float4* wr = reinterpret_cast<const float4*>(
            W + ((size_t)s * K_CODE + besti) * D_DIM);
        float4* orow = reinterpret_cast<float4*>(
            out + (size_t)(n0 + r) * IN_DIM + s * D_DIM);
        float ls = 0.f;
#pragma unroll
        for (int j = 0; j < 8; j++) {
            float4 vv = __ldg(&wr[j]);
            float a0 = vv.x - zr[j * 4 + 0];
            float a1 = vv.y - zr[j * 4 + 1];
            float a2 = vv.z - zr[j * 4 + 2];
            float a3 = vv.w - zr[j * 4 + 3];
            ls = fmaf(a0, a0, ls); ls = fmaf(a1, a1, ls);
            ls = fmaf(a2, a2, ls); ls = fmaf(a3, a3, ls);
            orow[j] = vv;
        }
        s_loss[r] = ls;
    }
    __syncthreads();

    if (tid == 0) {
        float acc = 0.f;
#pragma unroll
        for (int q = 0; q < M_TILE; q++) acc += s_loss[q];
        g_partial[s * MCTA + blockIdx.x] = acc;
    }

    // ---- fused deterministic finalize: last CTA reduces all partials ----
    __shared__ bool s_last;
    __threadfence();
    if (tid == 0) {
        unsigned int t = atomicAdd(&g_done, 1u);
        s_last = (t == (unsigned int)(NPART - 1));
    }
    __syncthreads();
    if (s_last) {
        float a = 0.f;
        for (int i = tid; i < NPART; i += THREADS) a += g_partial[i];   // fixed order
        float* red = s_candv;       // reuse (mainloop done in this CTA)
        red[tid] = a;
        __syncthreads();
#pragma unroll
        for (int off = 64; off > 0; off >>= 1) {
            if (tid < off) red[tid] += red[tid + off];
            __syncthreads();
        }
        if (tid == 0) {
            float mm = red[0] / (float)((size_t)N_TOK * S_CH * D_DIM);
            float loss = (float)S_CH * (mm + 0.001f * mm);
            if (out_size > N_TOK * IN_DIM) out[out_size - 1] = loss;
            g_done = 0;
        }
    }
}

// ---------------------------------------------------------------------------
extern "C" void kernel_launch(void* const* d_in, const int* in_sizes, int n_in,
                              void* d_out, int out_size) {
    const float* z = (const float*)d_in[0];   // (8192, 1024) f32
    const float* W = (const float*)d_in[1];   // (32, 1024, 32) f32
    float* out = (float*)d_out;

    cudaFuncSetAttribute(vq_main, cudaFuncAttributeMaxDynamicSharedMemorySize, SMEM_TOTAL);

    prep_w<<<(S_CH * K_CODE + 255) / 256, 256>>>(W);

    dim3 grid(MCTA, S_CH);
    vq_main<<<grid, THREADS, SMEM_TOTAL>>>(z, W, out, out_size);
}

// round 15
// speedup vs baseline: 1.0890x; 1.0006x over previous
#include <cuda_runtime.h>
#include <cuda_fp16.h>
#include <cstdint>

#define N_TOK   8192
#define S_CH    32
#define D_DIM   32
#define K_CODE  1024
#define IN_DIM  1024

#define M_TILE  128
#define THREADS 128
#define MCTA    (N_TOK / M_TILE)       // 64
#define NPART   (MCTA * S_CH)          // 2048

#define NCHUNK     8
#define CH_ROWS    128
#define ROW_BYTES  80                  // 32 halfs + 16B pad (ldmatrix bank-safe)
#define CH_BYTES   (CH_ROWS * ROW_BYTES)      // 10240

// ---------------- device scratch ----------------
__device__ float g_wsq[S_CH * K_CODE];
__device__ float g_partial[NPART];
__device__ unsigned int g_done = 0;
__device__ __align__(1024) unsigned char g_Wimg[S_CH * NCHUNK * CH_BYTES]; // 2.6MB

// ---------------- SMEM layout ----------------
#define SM_MBAR   0         // ready[0], ready[1], free[0], free[1] (8B each)
#define SM_WSQ    64        // 4096
#define SM_ZH     4160      // 128 x 80B = 10240 (half(-2z) image)
#define SM_CANDV  14400     // 128 x 12 packed f32 = 6144
#define SM_LOSS   20544     // 512
#define SM_B0     21504     // 10240 (1024-aligned)
#define SM_B1     31744     // 10240
#define SMEM_TOTAL 41984

// ---------------- PTX helpers ----------------
__device__ __forceinline__ uint32_t smem_u32(const void* p) {
    uint32_t a;
    asm("{ .reg .u64 t; cvta.to.shared.u64 t, %1; cvt.u32.u64 %0, t; }" : "=r"(a) : "l"(p));
    return a;
}
#define MBAR_INIT(a, c) \
    asm volatile("mbarrier.init.shared.b64 [%0], %1;" :: "r"(a), "r"(c) : "memory")
#define MBAR_EXPECT(a, b) \
    asm volatile("mbarrier.arrive.expect_tx.shared.b64 _, [%0], %1;" :: "r"(a), "r"(b) : "memory")
#define MBAR_ARRIVE(a) \
    asm volatile("mbarrier.arrive.shared.b64 _, [%0];" :: "r"(a) : "memory")
#define MBAR_WAIT(a, ph) do { \
    uint32_t _m = (a); uint32_t _p = (ph); uint32_t _d; \
    asm volatile("{\n\t.reg .pred p;\n\t" \
        "mbarrier.try_wait.parity.acquire.cta.shared::cta.b64 p, [%1], %2;\n\t" \
        "selp.b32 %0, 1, 0, p;\n\t}" : "=r"(_d) : "r"(_m), "r"(_p) : "memory"); \
    if (!_d) { \
        asm volatile("{\n\t.reg .pred P1;\n\t" \
            "WL_%=:\n\t" \
            "mbarrier.try_wait.parity.acquire.cta.shared::cta.b64 P1, [%0], %1, 0x989680;\n\t" \
            "@P1 bra.uni WD_%=;\n\t" \
            "bra.uni WL_%=;\n\t" \
            "WD_%=:\n\t}" :: "r"(_m), "r"(_p) : "memory"); \
    } } while (0)

__device__ __forceinline__ void bulk_copy(uint32_t dst, const void* src, uint32_t bytes, uint32_t mbar) {
    uint64_t g = (uint64_t)__cvta_generic_to_global(src);
    asm volatile("cp.async.bulk.shared::cta.global.mbarrier::complete_tx::bytes [%0], [%1], %2, [%3];"
        :: "r"(dst), "l"(g), "r"(bytes), "r"(mbar) : "memory");
}
#define LDM_X4(r0, r1, r2, r3, a) \
    asm volatile("ldmatrix.sync.aligned.m8n8.x4.shared.b16 {%0,%1,%2,%3}, [%4];" \
        : "=r"(r0), "=r"(r1), "=r"(r2), "=r"(r3) : "r"(a))
#define MMA16816(c, a, b0, b1) \
    asm volatile("mma.sync.aligned.m16n8k16.row.col.f32.f16.f16.f32 " \
        "{%0,%1,%2,%3}, {%4,%5,%6,%7}, {%8,%9}, {%0,%1,%2,%3};" \
        : "+f"((c)[0]), "+f"((c)[1]), "+f"((c)[2]), "+f"((c)[3]) \
        : "r"((a)[0]), "r"((a)[1]), "r"((a)[2]), "r"((a)[3]), "r"(b0), "r"(b1))
#define MMA16816_INIT(c, a, b0, b1, c0v, c1v) \
    asm volatile("mma.sync.aligned.m16n8k16.row.col.f32.f16.f16.f32 " \
        "{%0,%1,%2,%3}, {%4,%5,%6,%7}, {%8,%9}, {%10,%11,%12,%13};" \
        : "=f"((c)[0]), "=f"((c)[1]), "=f"((c)[2]), "=f"((c)[3]) \
        : "r"((a)[0]), "r"((a)[1]), "r"((a)[2]), "r"((a)[3]), "r"(b0), "r"(b1), \
          "f"(c0v), "f"(c1v), "f"(c0v), "f"(c1v))

// pack k (10 bits) into low mantissa bits: ordering-preserving up to ~1.5e-2 abs
#define PPACK(v, k) __uint_as_float((__float_as_uint(v) & 0xFFFFFC00u) | (uint32_t)(k))

// per-row group epilogue: sorted lowest-2-of-4 network + merge into sorted top-3
#define LOW2MERGE(rw, v0, v1, v2, v3) do { \
    float _p0 = PPACK(v0, col0); \
    float _p1 = PPACK(v1, col0 + 1); \
    float _p2 = PPACK(v2, col2); \
    float _p3 = PPACK(v3, col2 + 1); \
    float _s1 = fminf(_p0, _p1), _t1 = fmaxf(_p0, _p1); \
    float _s2 = fminf(_p2, _p3), _t2 = fmaxf(_p2, _p3); \
    float _lo = fminf(_s1, _s2); \
    float _sec = fminf(fmaxf(_s1, _s2), fminf(_t1, _t2)); \
    float _m1 = fminf(c1[rw], _lo), _M1 = fmaxf(c1[rw], _lo); \
    float _m2 = fminf(c2[rw], _sec); \
    c1[rw] = _m1; \
    float _mx = fmaxf(_M1, _m2); \
    c2[rw] = fminf(_M1, _m2); \
    c3[rw] = fminf(c3[rw], _mx); } while (0)

// ---------------------------------------------------------------------------
// Kernel 1: prep — wsq + fp16 W image; row staged in regs, 5x ST.128
// ---------------------------------------------------------------------------
__global__ void prep_w(const float* __restrict__ W) {
    int i = blockIdx.x * blockDim.x + threadIdx.x;   // s*1024 + k
    if (i >= S_CH * K_CODE) return;
    int k = i & (K_CODE - 1);
    int s = i >> 10;
    int chunk = k >> 7, row = k & (CH_ROWS - 1);
    const float4* wr = reinterpret_cast<const float4*>(W + (size_t)i * D_DIM);

    float4 stage[5];
    __half2* oh = reinterpret_cast<__half2*>(stage);
    float sq = 0.f;
#pragma unroll
    for (int j = 0; j < 8; j++) {
        float4 v = __ldg(&wr[j]);
        sq = fmaf(v.x, v.x, sq); sq = fmaf(v.y, v.y, sq);
        sq = fmaf(v.z, v.z, sq); sq = fmaf(v.w, v.w, sq);
        oh[j * 2 + 0] = __floats2half2_rn(v.x, v.y);
        oh[j * 2 + 1] = __floats2half2_rn(v.z, v.w);
    }
#pragma unroll
    for (int j = 16; j < 20; j++) oh[j] = __floats2half2_rn(0.f, 0.f);

    float4* dst = reinterpret_cast<float4*>(
        g_Wimg + (size_t)(s * NCHUNK + chunk) * CH_BYTES + (size_t)row * ROW_BYTES);
#pragma unroll
    for (int j = 0; j < 5; j++) dst[j] = stage[j];
    g_wsq[i] = sq;
}

// ---------------------------------------------------------------------------
// Kernel 2: main — 4-warp CTA, warp-decoupled, CONTINUOUS cross-chunk
// software pipeline (no drain/prologue seams), packed top-3
// ---------------------------------------------------------------------------
__global__ __launch_bounds__(THREADS, 4)
void vq_main(const float* __restrict__ z,
             const float* __restrict__ W,
             float* __restrict__ out,
             int out_size)
{
    extern __shared__ char smem[];
    const uint32_t sb = smem_u32(smem);
    const int tid  = threadIdx.x;
    const int wid  = tid >> 5;
    const int lane = tid & 31;
    const int s    = blockIdx.y;
    const int n0   = blockIdx.x * M_TILE;

    float* s_wsq   = reinterpret_cast<float*>(smem + SM_WSQ);
    float* s_candv = reinterpret_cast<float*>(smem + SM_CANDV);
    float* s_loss  = reinterpret_cast<float*>(smem + SM_LOSS);

    const uint32_t mb_ready0 = sb + SM_MBAR;
    const uint32_t mb_ready1 = sb + SM_MBAR + 8;
    const uint32_t mb_free0  = sb + SM_MBAR + 16;
    const uint32_t mb_free1  = sb + SM_MBAR + 24;

    if (tid == 0) {
        MBAR_INIT(mb_ready0, 1); MBAR_INIT(mb_ready1, 1);
        MBAR_INIT(mb_free0, THREADS); MBAR_INIT(mb_free1, THREADS);
    }
    __syncthreads();

    if (tid == 0) {
        MBAR_EXPECT(mb_ready0, CH_BYTES);
        bulk_copy(sb + SM_B0, g_Wimg + (size_t)(s * NCHUNK + 0) * CH_BYTES, CH_BYTES, mb_ready0);
        MBAR_EXPECT(mb_ready1, CH_BYTES);
        bulk_copy(sb + SM_B1, g_Wimg + (size_t)(s * NCHUNK + 1) * CH_BYTES, CH_BYTES, mb_ready1);
    }

    // ---- stage A image half(-2z): one row per thread, + wsq ----
    {
        const int r = tid;                      // 0..127
        const float4* zr = reinterpret_cast<const float4*>(
            z + (size_t)(n0 + r) * IN_DIM + s * D_DIM);
        float4 stage[5];
        __half2* zh = reinterpret_cast<__half2*>(stage);
#pragma unroll
        for (int j = 0; j < 4; j++) {
            float4 v0 = __ldg(&zr[j * 2 + 0]);
            float4 v1 = __ldg(&zr[j * 2 + 1]);
            zh[j * 4 + 0] = __floats2half2_rn(-2.f * v0.x, -2.f * v0.y);
            zh[j * 4 + 1] = __floats2half2_rn(-2.f * v0.z, -2.f * v0.w);
            zh[j * 4 + 2] = __floats2half2_rn(-2.f * v1.x, -2.f * v1.y);
            zh[j * 4 + 3] = __floats2half2_rn(-2.f * v1.z, -2.f * v1.w);
        }
#pragma unroll
        for (int j = 16; j < 20; j++) zh[j] = __floats2half2_rn(0.f, 0.f);
        float4* dst = reinterpret_cast<float4*>(smem + SM_ZH + r * ROW_BYTES);
#pragma unroll
        for (int j = 0; j < 5; j++) dst[j] = stage[j];
#pragma unroll
        for (int j = 0; j < K_CODE / THREADS; j++)
            s_wsq[tid + j * THREADS] = g_wsq[s * K_CODE + tid + j * THREADS];
    }
    __syncthreads();   // A image + wsq visible to all warps

    // ---- A fragments: 2 m16 blocks x 2 k-steps ----
    uint32_t Ah[2][2][4];
    {
        const int kb = (lane >> 4) & 1;
#pragma unroll
        for (int mb = 0; mb < 2; mb++) {
            const int rowoff = wid * 32 + mb * 16 + ((lane >> 3) & 1) * 8 + (lane & 7);
#pragma unroll
            for (int ks = 0; ks < 2; ks++) {
                uint32_t a = sb + SM_ZH + rowoff * ROW_BYTES + ks * 32 + kb * 16;
                LDM_X4(Ah[mb][ks][0], Ah[mb][ks][1], Ah[mb][ks][2], Ah[mb][ks][3], a);
            }
        }
    }

    const int g   = lane >> 2;
    const int tig = lane & 3;

    // per-thread: 4 row-streams (rows wid*32 + g + {0,8,16,24}), sorted top-3
    float c1[4], c2[4], c3[4];
#pragma unroll
    for (int c = 0; c < 4; c++) { c1[c] = 3.4e38f; c2[c] = 3.4e38f; c3[c] = 3.4e38f; }

    const int bnrow = ((lane & 16) ? 8 : 0) + (lane & 7);
    const int bkb   = (lane >> 3) & 1;
    const uint32_t bbase = (uint32_t)bnrow * ROW_BYTES + bkb * 16;

    // double-buffered fragments / wsq / accumulators (continuous pipeline)
    uint32_t bh0[2][4], bh1[2][4];
    float2   w01b[2], w23b[2];
    float a00[2][4], a01[2][4], a10[2][4], a11[2][4];

    // ---- global prologue: wait chunk 0, load fragments for gg = 0 ----
    MBAR_WAIT(mb_ready0, 0);
    LDM_X4(bh0[0][0], bh0[0][1], bh0[0][2], bh0[0][3], sb + SM_B0 + bbase);
    LDM_X4(bh1[0][0], bh1[0][1], bh1[0][2], bh1[0][3], sb + SM_B0 + bbase + 32);
    w01b[0] = *reinterpret_cast<const float2*>(&s_wsq[tig * 2]);
    w23b[0] = *reinterpret_cast<const float2*>(&s_wsq[8 + tig * 2]);

#pragma unroll 1
    for (int c = 0; c < NCHUNK; c++) {
        const uint32_t whb   = sb + ((c & 1) ? SM_B1 : SM_B0);
        const uint32_t whb_n = sb + ((c & 1) ? SM_B0 : SM_B1);
        const int kch = c * CH_ROWS;

#pragma unroll
        for (int g2 = 0; g2 < 8; g2++) {
            const int cur = g2 & 1, nxt = cur ^ 1;

            // 1) prefetch fragments + wsq for the NEXT iteration (cross-chunk!)
            if (g2 < 7) {
                const uint32_t boff = bbase + (uint32_t)(g2 + 1) * (16 * ROW_BYTES);
                LDM_X4(bh0[nxt][0], bh0[nxt][1], bh0[nxt][2], bh0[nxt][3], whb + boff);
                LDM_X4(bh1[nxt][0], bh1[nxt][1], bh1[nxt][2], bh1[nxt][3], whb + boff + 32);
                const int kb2 = kch + (g2 + 1) * 16;
                w01b[nxt] = *reinterpret_cast<const float2*>(&s_wsq[kb2 + tig * 2]);
                w23b[nxt] = *reinterpret_cast<const float2*>(&s_wsq[kb2 + 8 + tig * 2]);
            } else if (c + 1 < NCHUNK) {
                // per-thread wait for next chunk's data, then prefetch its g2=0
                MBAR_WAIT((c & 1) ? mb_ready0 : mb_ready1, ((c + 1) >> 1) & 1);
                LDM_X4(bh0[nxt][0], bh0[nxt][1], bh0[nxt][2], bh0[nxt][3], whb_n + bbase);
                LDM_X4(bh1[nxt][0], bh1[nxt][1], bh1[nxt][2], bh1[nxt][3], whb_n + bbase + 32);
                const int kb2 = (c + 1) * CH_ROWS;
                w01b[nxt] = *reinterpret_cast<const float2*>(&s_wsq[kb2 + tig * 2]);
                w23b[nxt] = *reinterpret_cast<const float2*>(&s_wsq[kb2 + 8 + tig * 2]);
            }

            // 2) MMAs for this iteration (fragments loaded last iteration)
            MMA16816_INIT(a00[cur], Ah[0][0], bh0[cur][0], bh0[cur][1], w01b[cur].x, w01b[cur].y);
            MMA16816     (a00[cur], Ah[0][1], bh1[cur][0], bh1[cur][1]);
            MMA16816_INIT(a01[cur], Ah[0][0], bh0[cur][2], bh0[cur][3], w23b[cur].x, w23b[cur].y);
            MMA16816     (a01[cur], Ah[0][1], bh1[cur][2], bh1[cur][3]);
            MMA16816_INIT(a10[cur], Ah[1][0], bh0[cur][0], bh0[cur][1], w01b[cur].x, w01b[cur].y);
            MMA16816     (a10[cur], Ah[1][1], bh1[cur][0], bh1[cur][1]);
            MMA16816_INIT(a11[cur], Ah[1][0], bh0[cur][2], bh0[cur][3], w23b[cur].x, w23b[cur].y);
            MMA16816     (a11[cur], Ah[1][1], bh1[cur][2], bh1[cur][3]);

            // 3) epilogue for the PREVIOUS iteration (slot nxt), cross-chunk uniform
            if (c > 0 || g2 > 0) {
                const int kbase = kch + (g2 - 1) * 16;   // ok across chunks: g2=0 -> kch-16
                const int col0 = kbase + tig * 2;
                const int col2 = kbase + 8 + tig * 2;
                LOW2MERGE(0, a00[nxt][0], a00[nxt][1], a01[nxt][0], a01[nxt][1]);
                LOW2MERGE(1, a00[nxt][2], a00[nxt][3], a01[nxt][2], a01[nxt][3]);
                LOW2MERGE(2, a10[nxt][0], a10[nxt][1], a11[nxt][0], a11[nxt][1]);
                LOW2MERGE(3, a10[nxt][2], a10[nxt][3], a11[nxt][2], a11[nxt][3]);
            }
        }

        // release buffer c (last smem read of it was the prefetch at g2==6)
        MBAR_ARRIVE((c & 1) ? mb_free1 : mb_free0);
        if (tid == 0 && c + 2 < NCHUNK) {
            MBAR_WAIT((c & 1) ? mb_free1 : mb_free0, (c >> 1) & 1);
            MBAR_EXPECT((c & 1) ? mb_ready1 : mb_ready0, CH_BYTES);
            bulk_copy(whb, g_Wimg + (size_t)(s * NCHUNK + c + 2) * CH_BYTES, CH_BYTES,
                      (c & 1) ? mb_ready1 : mb_ready0);
        }
    }

    // ---- global drain: epilogue for gg = 63 (slot 1) ----
    {
        const int kbase = 7 * CH_ROWS + 7 * 16;
        const int col0 = kbase + tig * 2;
        const int col2 = kbase + 8 + tig * 2;
        LOW2MERGE(0, a00[1][0], a00[1][1], a01[1][0], a01[1][1]);
        LOW2MERGE(1, a00[1][2], a00[1][3], a01[1][2], a01[1][3]);
        LOW2MERGE(2, a10[1][0], a10[1][1], a11[1][0], a11[1][1]);
        LOW2MERGE(3, a10[1][2], a10[1][3], a11[1][2], a11[1][3]);
    }

    // ---- dump candidates: 12 packed per row (4 threads x top-3) ----
    {
        const int r0 = wid * 32 + g;
#pragma unroll
        for (int t = 0; t < 4; t++) {
            const int r = r0 + t * 8;
            s_candv[r * 12 + tig * 3 + 0] = c1[t];
            s_candv[r * 12 + tig * 3 + 1] = c2[t];
            s_candv[r * 12 + tig * 3 + 2] = c3[t];
        }
    }
    __syncwarp();   // candidates are warp-local: warp w owns rows 32w..32w+31

    // ---- band-filtered exact fp32 recheck: one thread per row ----
    {
        const int r = tid;
        float zr[D_DIM];
        {
            const float4* zg = reinterpret_cast<const float4*>(
                z + (size_t)(n0 + r) * IN_DIM + s * D_DIM);
#pragma unroll
            for (int j = 0; j < 8; j++) {
                float4 v = __ldg(&zg[j]);
                zr[j * 4 + 0] = v.x; zr[j * 4 + 1] = v.y;
                zr[j * 4 + 2] = v.z; zr[j * 4 + 3] = v.w;
            }
        }
        float zsq = 0.f;
#pragma unroll
        for (int d = 0; d < D_DIM; d++) zsq = fmaf(zr[d], zr[d], zsq);

        float m = 3.4e38f;
#pragma unroll
        for (int j = 0; j < 12; j++) m = fminf(m, s_candv[r * 12 + j]);
        const float thr = m + 0.06f;

        float bestd = 3.4e38f;
        int   besti = K_CODE;
#pragma unroll 1
        for (int j = 0; j < 12; j++) {
            float pv = s_candv[r * 12 + j];
            if (pv > thr) continue;
            int k = (int)(__float_as_uint(pv) & 0x3FFu);
            const float4* wr = reinterpret_cast<const float4*>(
                W + ((size_t)s * K_CODE + k) * D_DIM);
            float dot = 0.f;
#pragma unroll
            for (int jj = 0; jj < 8; jj++) {
                float4 vv = __ldg(&wr[jj]);
                dot = fmaf(zr[jj * 4 + 0], vv.x, dot);
                dot = fmaf(zr[jj * 4 + 1], vv.y, dot);
                dot = fmaf(zr[jj * 4 + 2], vv.z, dot);
                dot = fmaf(zr[jj * 4 + 3], vv.w, dot);
            }
            float d2 = (zsq + s_wsq[k]) - 2.0f * dot;
            if (d2 < bestd || (d2 == bestd && k < besti)) { bestd = d2; besti = k; }
        }

        // gather winner, write output row-chunk, loss contribution
        const float4* wr = reinterpret_cast<const float4*>(
            W + ((size_t)s * K_CODE + besti) * D_DIM);
        float4* orow = reinterpret_cast<float4*>(
            out + (size_t)(n0 + r) * IN_DIM + s * D_DIM);
        float ls = 0.f;
#pragma unroll
        for (int j = 0; j < 8; j++) {
            float4 vv = __ldg(&wr[j]);
            float a0 = vv.x - zr[j * 4 + 0];
            float a1 = vv.y - zr[j * 4 + 1];
            float a2 = vv.z - zr[j * 4 + 2];
            float a3 = vv.w - zr[j * 4 + 3];
            ls = fmaf(a0, a0, ls); ls = fmaf(a1, a1, ls);
            ls = fmaf(a2, a2, ls); ls = fmaf(a3, a3, ls);
            orow[j] = vv;
        }
        s_loss[r] = ls;
    }
    __syncthreads();

    if (tid == 0) {
        float acc = 0.f;
#pragma unroll
        for (int q = 0; q < M_TILE; q++) acc += s_loss[q];
        g_partial[s * MCTA + blockIdx.x] = acc;
    }

    // ---- fused deterministic finalize: last CTA reduces all partials ----
    __shared__ bool s_last;
    __threadfence();
    if (tid == 0) {
        unsigned int t = atomicAdd(&g_done, 1u);
        s_last = (t == (unsigned int)(NPART - 1));
    }
    __syncthreads();
    if (s_last) {
        float a = 0.f;
        for (int i = tid; i < NPART; i += THREADS) a += g_partial[i];   // fixed order
        float* red = s_candv;       // reuse (mainloop done in this CTA)
        red[tid] = a;
        __syncthreads();
#pragma unroll
        for (int off = 64; off > 0; off >>= 1) {
            if (tid < off) red[tid] += red[tid + off];
            __syncthreads();
        }
        if (tid == 0) {
            float mm = red[0] / (float)((size_t)N_TOK * S_CH * D_DIM);
            float loss = (float)S_CH * (mm + 0.001f * mm);
            if (out_size > N_TOK * IN_DIM) out[out_size - 1] = loss;
            g_done = 0;
        }
    }
}

// ---------------------------------------------------------------------------
extern "C" void kernel_launch(void* const* d_in, const int* in_sizes, int n_in,
                              void* d_out, int out_size) {
    const float* z = (const float*)d_in[0];   // (8192, 1024) f32
    const float* W = (const float*)d_in[1];   // (32, 1024, 32) f32
    float* out = (float*)d_out;

    cudaFuncSetAttribute(vq_main, cudaFuncAttributeMaxDynamicSharedMemorySize, SMEM_TOTAL);

    prep_w<<<(S_CH * K_CODE + 255) / 256, 256>>>(W);

    dim3 grid(MCTA, S_CH);
    vq_main<<<grid, THREADS, SMEM_TOTAL>>>(z, W, out, out_size);
}